// round 6
// baseline (speedup 1.0000x reference)
#include <cuda_runtime.h>
#include <cuda_fp16.h>

#define MAXN  100000
#define MAXE  600000
#define NG    512
#define H     128
#define NVOC  4096
#define PART  16     // warp-shares per graph in conv2

// ---- scratch (static __device__ globals; allocation-free) ----
__device__ int   g_deg[MAXN];
__device__ int   g_cursor[MAXN];
__device__ int   g_rowptr[MAXN + 1];
__device__ int   g_csr[MAXE];     // src node id per edge (grouped by dst)
__device__ int   g_csrx[MAXE];    // x[src] per edge
__device__ float g_csrw[MAXE];    // dis[src] per edge
__device__ float g_dis[MAXN];
__device__ uint2 g_embW1h[NVOC * H / 4];          // fp16 table, 1 MB
__device__ uint2 g_h1h[(size_t)MAXN * H / 4];     // fp16 h1, 25.6 MB
__device__ float g_gsum[NG * H];
__device__ int   g_gcnt[NG];
__device__ int   g_gstart[NG + 1];
__device__ int   g_pref[128];
__device__ volatile int g_flag[128];

// ---- fused: embW1 = emb @ W1 (fp16 out)  +  zero accumulators/flags ----
__global__ void k_prep(const float* __restrict__ emb, const float* __restrict__ W1, int N) {
    int b = blockIdx.x;
    if (b < 128) {
        int j = threadIdx.x;
        int r0 = b * 32;
        __half* T = (__half*)g_embW1h;
        for (int r = r0; r < r0 + 32; r++) {
            const float* er = emb + (size_t)r * H;
            float acc = 0.f;
#pragma unroll 8
            for (int k = 0; k < H; k++) acc = fmaf(__ldg(er + k), W1[k * H + j], acc);
            T[(size_t)r * H + j] = __float2half_rn(acc);
        }
    } else {
        int i = (b - 128) * blockDim.x + threadIdx.x;
        int stride = 128 * blockDim.x;
        for (int t = i; t < N; t += stride) { g_deg[t] = 0; g_cursor[t] = 0; }
        for (int t = i; t < NG * H; t += stride) g_gsum[t] = 0.f;
        for (int t = i; t < NG; t += stride) g_gcnt[t] = 0;
        for (int t = i; t < 128; t += stride) { g_flag[t] = 0; }
    }
}

// ---- in-degree count + per-graph node count ----
__global__ void k_count(const int* __restrict__ dst, int E,
                        const int* __restrict__ batch, int N) {
    __shared__ int hist[NG];
    for (int i = threadIdx.x; i < NG; i += blockDim.x) hist[i] = 0;
    __syncthreads();
    int i0 = blockIdx.x * blockDim.x + threadIdx.x;
    int stride = gridDim.x * blockDim.x;
    for (int e = i0; e < E; e += stride) atomicAdd(&g_deg[dst[e]], 1);
    for (int v = i0; v < N; v += stride) atomicAdd(&hist[batch[v]], 1);
    __syncthreads();
    for (int i = threadIdx.x; i < NG; i += blockDim.x)
        if (hist[i]) atomicAdd(&g_gcnt[i], hist[i]);
}

// ---- single-kernel domino scan: deg -> rowptr (+dis), gcnt -> gstart ----
// nb <= 128 blocks, all co-resident in wave 1 (<= 148 SMs), so the
// predecessor spin cannot deadlock.
__global__ void k_scan(int N, int E) {
    __shared__ int s[1024];
    __shared__ int sprefix;
    int b = blockIdx.x, t = threadIdx.x;
    int i = b * 1024 + t;
    int v = (i < N) ? g_deg[i] : 0;
    s[t] = v;
    __syncthreads();
    for (int off = 1; off < 1024; off <<= 1) {
        int u = (t >= off) ? s[t - off] : 0;
        __syncthreads();
        s[t] += u;
        __syncthreads();
    }
    if (t == 0) {
        int pref = 0;
        if (b > 0) {
            while (g_flag[b - 1] == 0) { }
            pref = *(volatile int*)&g_pref[b - 1];
        }
        g_pref[b] = pref + s[1023];
        __threadfence();
        g_flag[b] = 1;
        sprefix = pref;
    }
    __syncthreads();
    if (i < N) {
        g_rowptr[i] = sprefix + s[t] - v;     // exclusive
        g_dis[i] = rsqrtf((float)(v + 1));    // +1 self-loop
    }
    if (i == 0) g_rowptr[N] = E;

    // block 0 additionally scans gcnt -> gstart (512 values)
    if (b == 0) {
        __shared__ int gs[NG];
        if (t < NG) gs[t] = g_gcnt[t];
        __syncthreads();
        for (int off = 1; off < NG; off <<= 1) {
            int u = (t < NG && t >= off) ? gs[t - off] : 0;
            __syncthreads();
            if (t < NG) gs[t] += u;
            __syncthreads();
        }
        if (t < NG) g_gstart[t + 1] = gs[t];
        if (t == 0) g_gstart[0] = 0;
    }
}

// ---- fill CSR + per-edge precompute of x[src], dis[src] ----
__global__ void k_fill(const int* __restrict__ src, const int* __restrict__ dst,
                       const int* __restrict__ x, int E) {
    int i0 = blockIdx.x * blockDim.x + threadIdx.x;
    int stride = gridDim.x * blockDim.x;
    for (int e = i0; e < E; e += stride) {
        int d = dst[e];
        int s = src[e];
        int pos = atomicAdd(&g_cursor[d], 1);
        int idx = g_rowptr[d] + pos;
        g_csr[idx]  = s;
        g_csrx[idx] = x[s];
        g_csrw[idx] = g_dis[s];
    }
}

__device__ __forceinline__ void fma_row(uint2 u, float w,
                                        float& ax, float& ay, float& az, float& aw) {
    float2 f0 = __half22float2(*(__half2*)&u.x);
    float2 f1 = __half22float2(*(__half2*)&u.y);
    ax = fmaf(w, f0.x, ax); ay = fmaf(w, f0.y, ay);
    az = fmaf(w, f1.x, az); aw = fmaf(w, f1.y, aw);
}

// ---- conv1: h1[v] = relu(b1 + sum_edges + self), unroll 4 ----
__global__ void k_conv1(const int* __restrict__ x, const float* __restrict__ b1, int N) {
    int v = (blockIdx.x * blockDim.x + threadIdx.x) >> 5;
    int lane = threadIdx.x & 31;
    if (v >= N) return;
    float dv = g_dis[v];
    const uint2* T = (const uint2*)g_embW1h;

    uint2 us = __ldg(&T[(size_t)__ldg(x + v) * 32 + lane]);
    float ax = 0.f, ay = 0.f, az = 0.f, aw = 0.f;
    fma_row(us, dv * dv, ax, ay, az, aw);

    int e = g_rowptr[v], e1 = g_rowptr[v + 1];
    for (; e + 3 < e1; e += 4) {
        int x0 = g_csrx[e],     x1 = g_csrx[e + 1];
        int x2 = g_csrx[e + 2], x3 = g_csrx[e + 3];
        float w0 = dv * g_csrw[e],     w1 = dv * g_csrw[e + 1];
        float w2 = dv * g_csrw[e + 2], w3 = dv * g_csrw[e + 3];
        uint2 u0 = __ldg(&T[(size_t)x0 * 32 + lane]);
        uint2 u1 = __ldg(&T[(size_t)x1 * 32 + lane]);
        uint2 u2 = __ldg(&T[(size_t)x2 * 32 + lane]);
        uint2 u3 = __ldg(&T[(size_t)x3 * 32 + lane]);
        fma_row(u0, w0, ax, ay, az, aw);
        fma_row(u1, w1, ax, ay, az, aw);
        fma_row(u2, w2, ax, ay, az, aw);
        fma_row(u3, w3, ax, ay, az, aw);
    }
    for (; e < e1; e++) {
        int x0 = g_csrx[e];
        float w0 = dv * g_csrw[e];
        uint2 u0 = __ldg(&T[(size_t)x0 * 32 + lane]);
        fma_row(u0, w0, ax, ay, az, aw);
    }
    float4 bb = ((const float4*)b1)[lane];
    float ox = fmaxf(ax + bb.x, 0.f), oy = fmaxf(ay + bb.y, 0.f);
    float oz = fmaxf(az + bb.z, 0.f), ow = fmaxf(aw + bb.w, 0.f);
    __half2 p0 = __floats2half2_rn(ox, oy);
    __half2 p1 = __floats2half2_rn(oz, ow);
    uint2 o;
    o.x = *(unsigned*)&p0; o.y = *(unsigned*)&p1;
    g_h1h[(size_t)v * 32 + lane] = o;
}

// ---- conv2 + pooling: graph-partitioned warps, one atomic flush per warp ----
__global__ void k_conv2pool() {
    int w = (blockIdx.x * blockDim.x + threadIdx.x) >> 5;
    int lane = threadIdx.x & 31;
    int g = w >> 4;         // graph id
    int p = w & (PART - 1); // share within graph
    if (g >= NG) return;
    int gs = g_gstart[g], ge = g_gstart[g + 1];
    int cnt = ge - gs;
    if (cnt <= 0) return;
    int len = (cnt + PART - 1) / PART;
    int v0 = gs + p * len;
    int v1 = min(v0 + len, ge);
    if (v0 >= v1) return;

    const uint2* Hm = g_h1h;
    float gx = 0.f, gy = 0.f, gz = 0.f, gwv = 0.f;

    for (int v = v0; v < v1; v++) {
        float dv = g_dis[v];
        float nx = 0.f, ny = 0.f, nz = 0.f, nw = 0.f;
        uint2 us = __ldg(&Hm[(size_t)v * 32 + lane]);
        fma_row(us, dv * dv, nx, ny, nz, nw);
        int e = g_rowptr[v], e1 = g_rowptr[v + 1];
        for (; e + 3 < e1; e += 4) {
            int s0 = g_csr[e],     s1 = g_csr[e + 1];
            int s2 = g_csr[e + 2], s3 = g_csr[e + 3];
            float w0 = dv * g_csrw[e],     w1 = dv * g_csrw[e + 1];
            float w2 = dv * g_csrw[e + 2], w3 = dv * g_csrw[e + 3];
            uint2 u0 = __ldg(&Hm[(size_t)s0 * 32 + lane]);
            uint2 u1 = __ldg(&Hm[(size_t)s1 * 32 + lane]);
            uint2 u2 = __ldg(&Hm[(size_t)s2 * 32 + lane]);
            uint2 u3 = __ldg(&Hm[(size_t)s3 * 32 + lane]);
            fma_row(u0, w0, nx, ny, nz, nw);
            fma_row(u1, w1, nx, ny, nz, nw);
            fma_row(u2, w2, nx, ny, nz, nw);
            fma_row(u3, w3, nx, ny, nz, nw);
        }
        for (; e < e1; e++) {
            int s0 = g_csr[e];
            float w0 = dv * g_csrw[e];
            uint2 u0 = __ldg(&Hm[(size_t)s0 * 32 + lane]);
            fma_row(u0, w0, nx, ny, nz, nw);
        }
        gx += nx; gy += ny; gz += nz; gwv += nw;
    }
    float* pdst = g_gsum + g * H + lane * 4;
    atomicAdd(pdst,     gx);
    atomicAdd(pdst + 1, gy);
    atomicAdd(pdst + 2, gz);
    atomicAdd(pdst + 3, gwv);
}

// ---- final: out[g] = (gsum[g] @ W2) / cnt[g] + b2 ----
__global__ void k_final(const float* __restrict__ W2, const float* __restrict__ b2,
                        float* __restrict__ out) {
    __shared__ float srow[H];
    int g = blockIdx.x, j = threadIdx.x;
    srow[j] = g_gsum[g * H + j];
    __syncthreads();
    float acc = 0.f;
#pragma unroll 8
    for (int k = 0; k < H; k++) acc = fmaf(srow[k], W2[k * H + j], acc);
    int c = g_gcnt[g];
    out[g * H + j] = (c > 0) ? (acc / (float)c + b2[j]) : 0.f;
}

extern "C" void kernel_launch(void* const* d_in, const int* in_sizes, int n_in,
                              void* d_out, int out_size) {
    const int*   x     = (const int*)d_in[0];
    const int*   ei    = (const int*)d_in[1];
    const int*   batch = (const int*)d_in[2];
    const float* emb   = (const float*)d_in[3];
    const float* W1    = (const float*)d_in[4];
    const float* b1    = (const float*)d_in[5];
    const float* W2    = (const float*)d_in[6];
    const float* b2    = (const float*)d_in[7];
    float* out = (float*)d_out;

    int N = in_sizes[0];
    int E = in_sizes[1] / 2;
    const int* src = ei;
    const int* dst = ei + E;

    k_prep<<<256, 128>>>(emb, W1, N);
    k_count<<<512, 256>>>(dst, E, batch, N);
    int nb = (N + 1023) / 1024;
    k_scan<<<nb, 1024>>>(N, E);
    k_fill<<<(E + 255) / 256, 256>>>(src, dst, x, E);
    k_conv1<<<((size_t)N * 32 + 255) / 256, 256>>>(x, b1, N);
    k_conv2pool<<<(NG * PART * 32) / 256, 256>>>();
    k_final<<<NG, H>>>(W2, b2, out);
}

// round 8
// speedup vs baseline: 1.5074x; 1.5074x over previous
#include <cuda_runtime.h>
#include <cuda_fp16.h>

#define MAXN  100000
#define MAXE  600000
#define NG    512
#define H     128
#define NVOC  4096

// ---- scratch (static __device__ globals; allocation-free) ----
__device__ int   g_deg[MAXN];
__device__ int   g_cursor[MAXN];
__device__ int   g_rowptr[MAXN + 1];
__device__ uint4 g_edge[MAXE];    // {src, x[src], bits(dis[src]), 0} per edge
__device__ float g_dis[MAXN];
__device__ uint2 g_embW1h[NVOC * H / 4];          // fp16 table, 1 MB
__device__ uint2 g_h1h[(size_t)MAXN * H / 4];     // fp16 h1, 25.6 MB
__device__ float g_gsum[NG * H];
__device__ int   g_gcnt[NG];
__device__ int   g_bsum[128];

// ---- fused: embW1 = emb @ W1 (fp16 out)  +  zero accumulators ----
__global__ void k_prep(const float* __restrict__ emb, const float* __restrict__ W1, int N) {
    int b = blockIdx.x;
    if (b < 128) {
        int j = threadIdx.x;
        int r0 = b * 32;
        __half* T = (__half*)g_embW1h;
        for (int r = r0; r < r0 + 32; r++) {
            const float* er = emb + (size_t)r * H;
            float acc = 0.f;
#pragma unroll 8
            for (int k = 0; k < H; k++) acc = fmaf(__ldg(er + k), W1[k * H + j], acc);
            T[(size_t)r * H + j] = __float2half_rn(acc);
        }
    } else {
        int i = (b - 128) * blockDim.x + threadIdx.x;
        int stride = 128 * blockDim.x;
        for (int t = i; t < N; t += stride) { g_deg[t] = 0; g_cursor[t] = 0; }
        for (int t = i; t < NG * H; t += stride) g_gsum[t] = 0.f;
        for (int t = i; t < NG; t += stride) g_gcnt[t] = 0;
    }
}

// ---- in-degree count + per-graph node count ----
__global__ void k_count(const int* __restrict__ dst, int E,
                        const int* __restrict__ batch, int N) {
    __shared__ int hist[NG];
    for (int i = threadIdx.x; i < NG; i += blockDim.x) hist[i] = 0;
    __syncthreads();
    int i0 = blockIdx.x * blockDim.x + threadIdx.x;
    int stride = gridDim.x * blockDim.x;
    for (int e = i0; e < E; e += stride) atomicAdd(&g_deg[dst[e]], 1);
    for (int v = i0; v < N; v += stride) atomicAdd(&hist[batch[v]], 1);
    __syncthreads();
    for (int i = threadIdx.x; i < NG; i += blockDim.x)
        if (hist[i]) atomicAdd(&g_gcnt[i], hist[i]);
}

// ---- 3-phase exclusive scan of g_deg -> g_rowptr ----
__global__ void k_scanA(int N) {
    __shared__ int s[1024];
    int i = blockIdx.x * 1024 + threadIdx.x;
    int v = (i < N) ? g_deg[i] : 0;
    s[threadIdx.x] = v;
    __syncthreads();
    for (int off = 512; off > 0; off >>= 1) {
        if (threadIdx.x < off) s[threadIdx.x] += s[threadIdx.x + off];
        __syncthreads();
    }
    if (threadIdx.x == 0) g_bsum[blockIdx.x] = s[0];
}

__global__ void k_scanB(int nb) {
    __shared__ int s[128];
    int t = threadIdx.x;
    int v = (t < nb && t < 128) ? g_bsum[t] : 0;
    s[t] = v;
    __syncthreads();
    for (int off = 1; off < 128; off <<= 1) {
        int u = (t >= off) ? s[t - off] : 0;
        __syncthreads();
        s[t] += u;
        __syncthreads();
    }
    if (t < nb && t < 128) g_bsum[t] = s[t] - v;   // exclusive
}

__global__ void k_scanC(int N, int E) {
    __shared__ int s[1024];
    int i = blockIdx.x * 1024 + threadIdx.x;
    int v = (i < N) ? g_deg[i] : 0;
    s[threadIdx.x] = v;
    __syncthreads();
    for (int off = 1; off < 1024; off <<= 1) {
        int u = (threadIdx.x >= (unsigned)off) ? s[threadIdx.x - off] : 0;
        __syncthreads();
        s[threadIdx.x] += u;
        __syncthreads();
    }
    if (i < N) {
        g_rowptr[i] = s[threadIdx.x] - v + g_bsum[blockIdx.x];
        g_dis[i] = rsqrtf((float)(v + 1));   // +1 self-loop
    }
    if (i == 0) g_rowptr[N] = E;
}

// ---- fill CSR: one packed 16B record per edge ----
__global__ void k_fill(const int* __restrict__ src, const int* __restrict__ dst,
                       const int* __restrict__ x, int E) {
    int i0 = blockIdx.x * blockDim.x + threadIdx.x;
    int stride = gridDim.x * blockDim.x;
    for (int e = i0; e < E; e += stride) {
        int d = dst[e];
        int s = src[e];
        int pos = atomicAdd(&g_cursor[d], 1);
        int idx = g_rowptr[d] + pos;
        float ws = g_dis[s];
        uint4 rec;
        rec.x = (unsigned)s;
        rec.y = (unsigned)x[s];
        rec.z = __float_as_uint(ws);
        rec.w = 0u;
        g_edge[idx] = rec;
    }
}

__device__ __forceinline__ void fma_row(uint2 u, float w,
                                        float& ax, float& ay, float& az, float& aw) {
    float2 f0 = __half22float2(*(__half2*)&u.x);
    float2 f1 = __half22float2(*(__half2*)&u.y);
    ax = fmaf(w, f0.x, ax); ay = fmaf(w, f0.y, ay);
    az = fmaf(w, f1.x, az); aw = fmaf(w, f1.y, aw);
}

// ---- conv1: h1[v] = relu(b1 + sum_edges + self), unroll 4 ----
__global__ void k_conv1(const int* __restrict__ x, const float* __restrict__ b1, int N) {
    int v = (blockIdx.x * blockDim.x + threadIdx.x) >> 5;
    int lane = threadIdx.x & 31;
    if (v >= N) return;
    float dv = g_dis[v];
    const uint2* T = (const uint2*)g_embW1h;

    uint2 us = __ldg(&T[(size_t)__ldg(x + v) * 32 + lane]);
    float ax = 0.f, ay = 0.f, az = 0.f, aw = 0.f;
    fma_row(us, dv * dv, ax, ay, az, aw);

    int e = g_rowptr[v], e1 = g_rowptr[v + 1];
    for (; e + 3 < e1; e += 4) {
        uint4 r0 = __ldg(&g_edge[e]);
        uint4 r1 = __ldg(&g_edge[e + 1]);
        uint4 r2 = __ldg(&g_edge[e + 2]);
        uint4 r3 = __ldg(&g_edge[e + 3]);
        uint2 u0 = __ldg(&T[(size_t)r0.y * 32 + lane]);
        uint2 u1 = __ldg(&T[(size_t)r1.y * 32 + lane]);
        uint2 u2 = __ldg(&T[(size_t)r2.y * 32 + lane]);
        uint2 u3 = __ldg(&T[(size_t)r3.y * 32 + lane]);
        fma_row(u0, dv * __uint_as_float(r0.z), ax, ay, az, aw);
        fma_row(u1, dv * __uint_as_float(r1.z), ax, ay, az, aw);
        fma_row(u2, dv * __uint_as_float(r2.z), ax, ay, az, aw);
        fma_row(u3, dv * __uint_as_float(r3.z), ax, ay, az, aw);
    }
    for (; e < e1; e++) {
        uint4 r0 = __ldg(&g_edge[e]);
        uint2 u0 = __ldg(&T[(size_t)r0.y * 32 + lane]);
        fma_row(u0, dv * __uint_as_float(r0.z), ax, ay, az, aw);
    }
    float4 bb = ((const float4*)b1)[lane];
    float ox = fmaxf(ax + bb.x, 0.f), oy = fmaxf(ay + bb.y, 0.f);
    float oz = fmaxf(az + bb.z, 0.f), ow = fmaxf(aw + bb.w, 0.f);
    __half2 p0 = __floats2half2_rn(ox, oy);
    __half2 p1 = __floats2half2_rn(oz, ow);
    uint2 o;
    o.x = *(unsigned*)&p0; o.y = *(unsigned*)&p1;
    g_h1h[(size_t)v * 32 + lane] = o;
}

// ---- conv2 scatter fused with graph pooling (batch is sorted), unroll 4 ----
__global__ void k_conv2pool(const int* __restrict__ batch, int N) {
    const int NPW = 4;
    int gw = (blockIdx.x * blockDim.x + threadIdx.x) >> 5;
    int lane = threadIdx.x & 31;
    int v0 = gw * NPW;
    if (v0 >= N) return;
    int v1 = min(v0 + NPW, N);
    const uint2* Hm = g_h1h;

    float gx = 0.f, gy = 0.f, gz = 0.f, gwv = 0.f;
    int curg = -1;
    for (int v = v0; v < v1; v++) {
        float dv = g_dis[v];
        float nx = 0.f, ny = 0.f, nz = 0.f, nw = 0.f;
        uint2 us = __ldg(&Hm[(size_t)v * 32 + lane]);
        fma_row(us, dv * dv, nx, ny, nz, nw);
        int e = g_rowptr[v], e1 = g_rowptr[v + 1];
        for (; e + 3 < e1; e += 4) {
            uint4 r0 = __ldg(&g_edge[e]);
            uint4 r1 = __ldg(&g_edge[e + 1]);
            uint4 r2 = __ldg(&g_edge[e + 2]);
            uint4 r3 = __ldg(&g_edge[e + 3]);
            uint2 u0 = __ldg(&Hm[(size_t)r0.x * 32 + lane]);
            uint2 u1 = __ldg(&Hm[(size_t)r1.x * 32 + lane]);
            uint2 u2 = __ldg(&Hm[(size_t)r2.x * 32 + lane]);
            uint2 u3 = __ldg(&Hm[(size_t)r3.x * 32 + lane]);
            fma_row(u0, dv * __uint_as_float(r0.z), nx, ny, nz, nw);
            fma_row(u1, dv * __uint_as_float(r1.z), nx, ny, nz, nw);
            fma_row(u2, dv * __uint_as_float(r2.z), nx, ny, nz, nw);
            fma_row(u3, dv * __uint_as_float(r3.z), nx, ny, nz, nw);
        }
        for (; e < e1; e++) {
            uint4 r0 = __ldg(&g_edge[e]);
            uint2 u0 = __ldg(&Hm[(size_t)r0.x * 32 + lane]);
            fma_row(u0, dv * __uint_as_float(r0.z), nx, ny, nz, nw);
        }
        int g = batch[v];
        if (g != curg) {
            if (curg >= 0) {
                float* p = g_gsum + curg * H + lane * 4;
                atomicAdd(p, gx); atomicAdd(p + 1, gy);
                atomicAdd(p + 2, gz); atomicAdd(p + 3, gwv);
            }
            curg = g; gx = nx; gy = ny; gz = nz; gwv = nw;
        } else {
            gx += nx; gy += ny; gz += nz; gwv += nw;
        }
    }
    if (curg >= 0) {
        float* p = g_gsum + curg * H + lane * 4;
        atomicAdd(p, gx); atomicAdd(p + 1, gy);
        atomicAdd(p + 2, gz); atomicAdd(p + 3, gwv);
    }
}

// ---- final: out[g] = (gsum[g] @ W2) / cnt[g] + b2 ----
__global__ void k_final(const float* __restrict__ W2, const float* __restrict__ b2,
                        float* __restrict__ out) {
    __shared__ float srow[H];
    int g = blockIdx.x, j = threadIdx.x;
    srow[j] = g_gsum[g * H + j];
    __syncthreads();
    float acc = 0.f;
#pragma unroll 8
    for (int k = 0; k < H; k++) acc = fmaf(srow[k], W2[k * H + j], acc);
    int c = g_gcnt[g];
    out[g * H + j] = (c > 0) ? (acc / (float)c + b2[j]) : 0.f;
}

extern "C" void kernel_launch(void* const* d_in, const int* in_sizes, int n_in,
                              void* d_out, int out_size) {
    const int*   x     = (const int*)d_in[0];
    const int*   ei    = (const int*)d_in[1];
    const int*   batch = (const int*)d_in[2];
    const float* emb   = (const float*)d_in[3];
    const float* W1    = (const float*)d_in[4];
    const float* b1    = (const float*)d_in[5];
    const float* W2    = (const float*)d_in[6];
    const float* b2    = (const float*)d_in[7];
    float* out = (float*)d_out;

    int N = in_sizes[0];
    int E = in_sizes[1] / 2;
    const int* src = ei;
    const int* dst = ei + E;

    k_prep<<<256, 128>>>(emb, W1, N);
    k_count<<<512, 256>>>(dst, E, batch, N);
    int nb = (N + 1023) / 1024;
    k_scanA<<<nb, 1024>>>(N);
    k_scanB<<<1, 128>>>(nb);
    k_scanC<<<nb, 1024>>>(N, E);
    k_fill<<<(E + 255) / 256, 256>>>(src, dst, x, E);
    k_conv1<<<((size_t)N * 32 + 255) / 256, 256>>>(x, b1, N);
    int warps2 = (N + 3) / 4;
    k_conv2pool<<<((size_t)warps2 * 32 + 255) / 256, 256>>>(batch, N);
    k_final<<<NG, H>>>(W2, b2, out);
}

// round 10
// speedup vs baseline: 2.2930x; 1.5211x over previous
#include <cuda_runtime.h>
#include <cuda_fp16.h>

#define MAXN  100000
#define MAXE  600000
#define NG    512
#define H     128
#define NVOC  4096

// ---- scratch (static __device__ globals; allocation-free) ----
__device__ int   g_deg[MAXN];
__device__ int   g_cursor[MAXN];
__device__ int   g_rowptr[MAXN + 1];
__device__ uint4 g_edge[MAXE];    // {src, x[src], bits(dis[src]), 0} per edge
__device__ float g_dis[MAXN];
__device__ uint2 g_embW1h[NVOC * H / 4];          // fp16 table, 1 MB
__device__ uint2 g_h1h[(size_t)MAXN * H / 4];     // fp16 h1, 25.6 MB
__device__ float g_gsum[NG * H];
__device__ int   g_gcnt[NG];
__device__ int   g_bsum[128];

// ---- fused: embW1 = emb @ W1 (fp16 out, 512 blocks)  +  zero accumulators ----
__global__ void k_prep(const float* __restrict__ emb, const float* __restrict__ W1, int N) {
    int b = blockIdx.x;
    if (b < 512) {
        int j = threadIdx.x;
        int r0 = b * 8;
        __half* T = (__half*)g_embW1h;
        for (int r = r0; r < r0 + 8; r++) {
            const float* er = emb + (size_t)r * H;
            float acc = 0.f;
#pragma unroll 8
            for (int k = 0; k < H; k++) acc = fmaf(__ldg(er + k), W1[k * H + j], acc);
            T[(size_t)r * H + j] = __float2half_rn(acc);
        }
    } else {
        int i = (b - 512) * blockDim.x + threadIdx.x;
        int stride = 128 * blockDim.x;
        for (int t = i; t < N; t += stride) { g_deg[t] = 0; g_cursor[t] = 0; }
        for (int t = i; t < NG * H; t += stride) g_gsum[t] = 0.f;
        for (int t = i; t < NG; t += stride) g_gcnt[t] = 0;
    }
}

// ---- in-degree count + per-graph node count ----
__global__ void k_count(const int* __restrict__ dst, int E,
                        const int* __restrict__ batch, int N) {
    __shared__ int hist[NG];
    for (int i = threadIdx.x; i < NG; i += blockDim.x) hist[i] = 0;
    __syncthreads();
    int i0 = blockIdx.x * blockDim.x + threadIdx.x;
    int stride = gridDim.x * blockDim.x;
    for (int e = i0; e < E; e += stride) atomicAdd(&g_deg[dst[e]], 1);
    for (int v = i0; v < N; v += stride) atomicAdd(&hist[batch[v]], 1);
    __syncthreads();
    for (int i = threadIdx.x; i < NG; i += blockDim.x)
        if (hist[i]) atomicAdd(&g_gcnt[i], hist[i]);
}

// ---- scan phase A: per-block sums ----
__global__ void k_scanA(int N) {
    __shared__ int s[1024];
    int i = blockIdx.x * 1024 + threadIdx.x;
    int v = (i < N) ? g_deg[i] : 0;
    s[threadIdx.x] = v;
    __syncthreads();
    for (int off = 512; off > 0; off >>= 1) {
        if (threadIdx.x < off) s[threadIdx.x] += s[threadIdx.x + off];
        __syncthreads();
    }
    if (threadIdx.x == 0) g_bsum[blockIdx.x] = s[0];
}

// ---- scan phase C (with inlined cross-block prefix): deg -> rowptr, dis ----
__global__ void k_scanC(int N, int E) {
    __shared__ int s[1024];
    __shared__ int sprefix;
    int t = threadIdx.x;
    int b = blockIdx.x;
    if (t == 0) sprefix = 0;
    int i = b * 1024 + t;
    int v = (i < N) ? g_deg[i] : 0;
    s[t] = v;
    __syncthreads();
    if (t < b) atomicAdd(&sprefix, g_bsum[t]);   // b <= 98 < 1024: one value/thread
    for (int off = 1; off < 1024; off <<= 1) {
        int u = (t >= off) ? s[t - off] : 0;
        __syncthreads();
        s[t] += u;
        __syncthreads();
    }
    if (i < N) {
        g_rowptr[i] = sprefix + s[t] - v;        // exclusive scan
        g_dis[i] = rsqrtf((float)(v + 1));       // +1 self-loop
    }
    if (i == 0) g_rowptr[N] = E;
}

// ---- fill CSR: one packed 16B record per edge ----
__global__ void k_fill(const int* __restrict__ src, const int* __restrict__ dst,
                       const int* __restrict__ x, int E) {
    int i0 = blockIdx.x * blockDim.x + threadIdx.x;
    int stride = gridDim.x * blockDim.x;
    for (int e = i0; e < E; e += stride) {
        int d = dst[e];
        int s = src[e];
        int pos = atomicAdd(&g_cursor[d], 1);
        int idx = g_rowptr[d] + pos;
        float ws = g_dis[s];
        uint4 rec;
        rec.x = (unsigned)s;
        rec.y = (unsigned)x[s];
        rec.z = __float_as_uint(ws);
        rec.w = 0u;
        g_edge[idx] = rec;
    }
}

__device__ __forceinline__ void fma_row(uint2 u, float w,
                                        float& ax, float& ay, float& az, float& aw) {
    float2 f0 = __half22float2(*(__half2*)&u.x);
    float2 f1 = __half22float2(*(__half2*)&u.y);
    ax = fmaf(w, f0.x, ax); ay = fmaf(w, f0.y, ay);
    az = fmaf(w, f1.x, az); aw = fmaf(w, f1.y, aw);
}

// ---- conv1: h1[v] = relu(b1 + sum_edges + self), unroll 4 ----
__global__ void k_conv1(const int* __restrict__ x, const float* __restrict__ b1, int N) {
    int v = (blockIdx.x * blockDim.x + threadIdx.x) >> 5;
    int lane = threadIdx.x & 31;
    if (v >= N) return;
    float dv = g_dis[v];
    const uint2* T = (const uint2*)g_embW1h;

    uint2 us = __ldg(&T[(size_t)__ldg(x + v) * 32 + lane]);
    float ax = 0.f, ay = 0.f, az = 0.f, aw = 0.f;
    fma_row(us, dv * dv, ax, ay, az, aw);

    int e = g_rowptr[v], e1 = g_rowptr[v + 1];
    for (; e + 3 < e1; e += 4) {
        uint4 r0 = __ldg(&g_edge[e]);
        uint4 r1 = __ldg(&g_edge[e + 1]);
        uint4 r2 = __ldg(&g_edge[e + 2]);
        uint4 r3 = __ldg(&g_edge[e + 3]);
        uint2 u0 = __ldg(&T[(size_t)r0.y * 32 + lane]);
        uint2 u1 = __ldg(&T[(size_t)r1.y * 32 + lane]);
        uint2 u2 = __ldg(&T[(size_t)r2.y * 32 + lane]);
        uint2 u3 = __ldg(&T[(size_t)r3.y * 32 + lane]);
        fma_row(u0, dv * __uint_as_float(r0.z), ax, ay, az, aw);
        fma_row(u1, dv * __uint_as_float(r1.z), ax, ay, az, aw);
        fma_row(u2, dv * __uint_as_float(r2.z), ax, ay, az, aw);
        fma_row(u3, dv * __uint_as_float(r3.z), ax, ay, az, aw);
    }
    for (; e < e1; e++) {
        uint4 r0 = __ldg(&g_edge[e]);
        uint2 u0 = __ldg(&T[(size_t)r0.y * 32 + lane]);
        fma_row(u0, dv * __uint_as_float(r0.z), ax, ay, az, aw);
    }
    float4 bb = ((const float4*)b1)[lane];
    float ox = fmaxf(ax + bb.x, 0.f), oy = fmaxf(ay + bb.y, 0.f);
    float oz = fmaxf(az + bb.z, 0.f), ow = fmaxf(aw + bb.w, 0.f);
    __half2 p0 = __floats2half2_rn(ox, oy);
    __half2 p1 = __floats2half2_rn(oz, ow);
    uint2 o;
    o.x = *(unsigned*)&p0; o.y = *(unsigned*)&p1;
    g_h1h[(size_t)v * 32 + lane] = o;
}

// ---- conv2 scatter fused with graph pooling (batch is sorted), unroll 4 ----
__global__ void k_conv2pool(const int* __restrict__ batch, int N) {
    const int NPW = 8;
    int gw = (blockIdx.x * blockDim.x + threadIdx.x) >> 5;
    int lane = threadIdx.x & 31;
    int v0 = gw * NPW;
    if (v0 >= N) return;
    int v1 = min(v0 + NPW, N);
    const uint2* Hm = g_h1h;

    float gx = 0.f, gy = 0.f, gz = 0.f, gwv = 0.f;
    int curg = -1;
    for (int v = v0; v < v1; v++) {
        float dv = g_dis[v];
        float nx = 0.f, ny = 0.f, nz = 0.f, nw = 0.f;
        uint2 us = __ldg(&Hm[(size_t)v * 32 + lane]);
        fma_row(us, dv * dv, nx, ny, nz, nw);
        int e = g_rowptr[v], e1 = g_rowptr[v + 1];
        for (; e + 3 < e1; e += 4) {
            uint4 r0 = __ldg(&g_edge[e]);
            uint4 r1 = __ldg(&g_edge[e + 1]);
            uint4 r2 = __ldg(&g_edge[e + 2]);
            uint4 r3 = __ldg(&g_edge[e + 3]);
            uint2 u0 = __ldg(&Hm[(size_t)r0.x * 32 + lane]);
            uint2 u1 = __ldg(&Hm[(size_t)r1.x * 32 + lane]);
            uint2 u2 = __ldg(&Hm[(size_t)r2.x * 32 + lane]);
            uint2 u3 = __ldg(&Hm[(size_t)r3.x * 32 + lane]);
            fma_row(u0, dv * __uint_as_float(r0.z), nx, ny, nz, nw);
            fma_row(u1, dv * __uint_as_float(r1.z), nx, ny, nz, nw);
            fma_row(u2, dv * __uint_as_float(r2.z), nx, ny, nz, nw);
            fma_row(u3, dv * __uint_as_float(r3.z), nx, ny, nz, nw);
        }
        for (; e < e1; e++) {
            uint4 r0 = __ldg(&g_edge[e]);
            uint2 u0 = __ldg(&Hm[(size_t)r0.x * 32 + lane]);
            fma_row(u0, dv * __uint_as_float(r0.z), nx, ny, nz, nw);
        }
        int g = batch[v];
        if (g != curg) {
            if (curg >= 0) {
                float* p = g_gsum + curg * H + lane * 4;
                atomicAdd(p, gx); atomicAdd(p + 1, gy);
                atomicAdd(p + 2, gz); atomicAdd(p + 3, gwv);
            }
            curg = g; gx = nx; gy = ny; gz = nz; gwv = nw;
        } else {
            gx += nx; gy += ny; gz += nz; gwv += nw;
        }
    }
    if (curg >= 0) {
        float* p = g_gsum + curg * H + lane * 4;
        atomicAdd(p, gx); atomicAdd(p + 1, gy);
        atomicAdd(p + 2, gz); atomicAdd(p + 3, gwv);
    }
}

// ---- final: out[g] = (gsum[g] @ W2) / cnt[g] + b2 ----
__global__ void k_final(const float* __restrict__ W2, const float* __restrict__ b2,
                        float* __restrict__ out) {
    __shared__ float srow[H];
    int g = blockIdx.x, j = threadIdx.x;
    srow[j] = g_gsum[g * H + j];
    __syncthreads();
    float acc = 0.f;
#pragma unroll 8
    for (int k = 0; k < H; k++) acc = fmaf(srow[k], W2[k * H + j], acc);
    int c = g_gcnt[g];
    out[g * H + j] = (c > 0) ? (acc / (float)c + b2[j]) : 0.f;
}

extern "C" void kernel_launch(void* const* d_in, const int* in_sizes, int n_in,
                              void* d_out, int out_size) {
    const int*   x     = (const int*)d_in[0];
    const int*   ei    = (const int*)d_in[1];
    const int*   batch = (const int*)d_in[2];
    const float* emb   = (const float*)d_in[3];
    const float* W1    = (const float*)d_in[4];
    const float* b1    = (const float*)d_in[5];
    const float* W2    = (const float*)d_in[6];
    const float* b2    = (const float*)d_in[7];
    float* out = (float*)d_out;

    int N = in_sizes[0];
    int E = in_sizes[1] / 2;
    const int* src = ei;
    const int* dst = ei + E;

    k_prep<<<640, 128>>>(emb, W1, N);
    k_count<<<512, 256>>>(dst, E, batch, N);
    int nb = (N + 1023) / 1024;
    k_scanA<<<nb, 1024>>>(N);
    k_scanC<<<nb, 1024>>>(N, E);
    k_fill<<<(E + 255) / 256, 256>>>(src, dst, x, E);
    k_conv1<<<((size_t)N * 32 + 255) / 256, 256>>>(x, b1, N);
    int warps2 = (N + 7) / 8;
    k_conv2pool<<<((size_t)warps2 * 32 + 255) / 256, 256>>>(batch, N);
    k_final<<<NG, H>>>(W2, b2, out);
}